// round 5
// baseline (speedup 1.0000x reference)
#include <cuda_runtime.h>
#include <stdint.h>

#define NB 8
#define NC 19
#define HH 512
#define WW 512
#define HW (HH * WW)          // 262144 pixels per batch, divisible by 4
#define NG (HW / 4)           // float4 groups per channel-plane = 65536
#define NREP 4                // shared accumulator replicas (one per warp % 4)
#define ROWP 20               // padded row stride (19 + 1) to spread banks

// Scratch (no allocations allowed)
__device__ float g_S[NB * NC * NC];   // S[b,i,k] = sum z[b,i,p] over pixels with label k
__device__ float g_cnt[NB * NC];      // cnt[b,k] = #pixels with label k
__device__ int   g_mode64;            // 1 if labels are int64 in memory, else 0 (int32)

// ---------------------------------------------------------------------------
// Kernel 0: zero scratch + detect label dtype.
// Reads words [0, 2*HW) of the label buffer as int32 — in-bounds for both
// int32 (NB*HW words) and int64 (2*NB*HW words) layouts. For little-endian
// int64 labels (values 0..18) every odd word is 0; for genuine int32 labels
// the odd words are uniform 0..18, so OR==0 has ~zero false-positive odds.
// ---------------------------------------------------------------------------
__global__ void __launch_bounds__(256)
setup_kernel(const int* __restrict__ lab32) {
    int t = blockIdx.x * blockDim.x + threadIdx.x;
    if (t < NB * NC * NC) g_S[t] = 0.0f;
    if (t < NB * NC)      g_cnt[t] = 0.0f;
    if (blockIdx.x == 0 && t == 0) g_mode64 = 1;  // assume int64 until disproven

    // OR-reduce odd words across the whole grid (12*256 = 3072 threads)
    int acc = 0;
    int nthreads = gridDim.x * blockDim.x;
    for (int i = t; i < HW; i += nthreads)        // odd word index = 2*i+1 < 2*HW
        acc |= lab32[2 * i + 1];
    // warp-reduce then one atomic per warp
    #pragma unroll
    for (int s = 16; s > 0; s >>= 1)
        acc |= __shfl_xor_sync(0xffffffffu, acc, s);
    if ((threadIdx.x & 31) == 0 && acc != 0)
        atomicExch(&g_mode64, 0);                 // nonzero odd word -> int32 labels
}

// ---------------------------------------------------------------------------
// Kernel 1: streaming scatter  S[b,i,label(p)] += z[b,i,p],  cnt[b,label] += 1
// blockIdx.y = batch. Grid-stride over float4 pixel groups.
// ---------------------------------------------------------------------------
__global__ void __launch_bounds__(256)
scatter_kernel(const float* __restrict__ seg, const int* __restrict__ lab32,
               int blocks_x) {
    __shared__ float S_sh[NREP][NC][ROWP];
    __shared__ float cnt_sh[NREP][NC];

    const int tid = threadIdx.x;
    for (int idx = tid; idx < NREP * NC * ROWP; idx += blockDim.x)
        (&S_sh[0][0][0])[idx] = 0.0f;
    for (int idx = tid; idx < NREP * NC; idx += blockDim.x)
        (&cnt_sh[0][0])[idx] = 0.0f;
    __syncthreads();

    const int b = blockIdx.y;
    const int r = (tid >> 5) & (NREP - 1);       // replica per warp
    const int mode64 = g_mode64;                  // uniform across grid

    const float4* z4 = (const float4*)(seg + (size_t)b * NC * HW);
    const int4*   l4 = mode64
        ? (const int4*)(lab32 + (size_t)b * HW * 2)   // int64 layout: 2 words/label
        : (const int4*)(lab32 + (size_t)b * HW);      // int32 layout

    const int stride = blocks_x * blockDim.x;
    for (int g = blockIdx.x * blockDim.x + tid; g < NG; g += stride) {
        int k0, k1, k2, k3;
        if (mode64) {
            int4 a = l4[2 * g];
            int4 c = l4[2 * g + 1];
            k0 = a.x; k1 = a.z; k2 = c.x; k3 = c.z;   // low words of each int64
        } else {
            int4 a = l4[g];
            k0 = a.x; k1 = a.y; k2 = a.z; k3 = a.w;
        }

        atomicAdd(&cnt_sh[r][k0], 1.0f);
        atomicAdd(&cnt_sh[r][k1], 1.0f);
        atomicAdd(&cnt_sh[r][k2], 1.0f);
        atomicAdd(&cnt_sh[r][k3], 1.0f);

        // Batch all 19 channel loads first (MLP = 19), then scatter.
        float4 v[NC];
#pragma unroll
        for (int i = 0; i < NC; i++)
            v[i] = z4[(size_t)i * NG + g];

#pragma unroll
        for (int i = 0; i < NC; i++) {
            atomicAdd(&S_sh[r][i][k0], v[i].x);
            atomicAdd(&S_sh[r][i][k1], v[i].y);
            atomicAdd(&S_sh[r][i][k2], v[i].z);
            atomicAdd(&S_sh[r][i][k3], v[i].w);
        }
    }
    __syncthreads();

    // Flush: reduce replicas, one global atomic per (i,k) / per k
    float* gS = g_S + (size_t)b * NC * NC;
    for (int idx = tid; idx < NC * NC; idx += blockDim.x) {
        int i = idx / NC, k = idx % NC;
        float s = 0.0f;
#pragma unroll
        for (int rr = 0; rr < NREP; rr++) s += S_sh[rr][i][k];
        atomicAdd(&gS[idx], s);
    }
    float* gC = g_cnt + (size_t)b * NC;
    for (int idx = tid; idx < NC; idx += blockDim.x) {
        float s = 0.0f;
#pragma unroll
        for (int rr = 0; rr < NREP; rr++) s += cnt_sh[rr][idx];
        atomicAdd(&gC[idx], s);
    }
}

// ---------------------------------------------------------------------------
// Kernel 2: finalize — 2888 log terms in double, write the scalar loss
//   alpha[b,i] = S[b,i,i]/cnt_i (0 if cnt_i==0)
//   beta[b,i,k] = (cnt_k - S[b,i,k])/cnt_k (0 if cnt_k==0)
//   loss = -0.5/B * sum log(0.5*(alpha + beta + eps))
// ---------------------------------------------------------------------------
__global__ void __launch_bounds__(256)
finalize_kernel(float* __restrict__ out) {
    __shared__ double red[256];
    const int tid = threadIdx.x;
    const double eps = 2.220446049250313e-16;  // np.spacing(1)

    double acc = 0.0;
    for (int idx = tid; idx < NB * NC * NC; idx += 256) {
        int b = idx / (NC * NC);
        int rem = idx % (NC * NC);
        int i = rem / NC, k = rem % NC;
        float cnt_i = g_cnt[b * NC + i];
        float cnt_k = g_cnt[b * NC + k];
        double alpha = (cnt_i > 0.0f)
            ? (double)g_S[b * NC * NC + i * NC + i] / (double)cnt_i : 0.0;
        double beta = (cnt_k > 0.0f)
            ? ((double)cnt_k - (double)g_S[b * NC * NC + i * NC + k]) / (double)cnt_k
            : 0.0;
        acc += log(0.5 * (alpha + beta + eps));
    }
    red[tid] = acc;
    __syncthreads();
    for (int s = 128; s > 0; s >>= 1) {
        if (tid < s) red[tid] += red[tid + s];
        __syncthreads();
    }
    if (tid == 0) out[0] = (float)(-0.5 * red[0] / (double)NB);
}

// ---------------------------------------------------------------------------
extern "C" void kernel_launch(void* const* d_in, const int* in_sizes, int n_in,
                              void* d_out, int out_size) {
    // Robust input identification by element count:
    //   seg_softmax: 8*19*512*512 = 39,845,888 ; labels: 8*512*512 = 2,097,152
    const float* seg;
    const int*   lab32;
    if (in_sizes[0] > in_sizes[1]) {
        seg   = (const float*)d_in[0];
        lab32 = (const int*)d_in[1];
    } else {
        seg   = (const float*)d_in[1];
        lab32 = (const int*)d_in[0];
    }
    float* out = (float*)d_out;

    setup_kernel<<<12, 256>>>(lab32);

    const int blocks_x = 37;                 // 37 * 8 = 296 CTAs, one wave @ 2/SM
    dim3 grid(blocks_x, NB);
    scatter_kernel<<<grid, 256>>>(seg, lab32, blocks_x);

    finalize_kernel<<<1, 256>>>(out);
}

// round 6
// speedup vs baseline: 1.9204x; 1.9204x over previous
#include <cuda_runtime.h>
#include <stdint.h>

#define NB 8
#define NC 19
#define HW (512 * 512)        // 262144 pixels per batch
#define TPX 512               // pixels per tile
#define NTILES (HW / TPX)     // 512 tiles per batch
#define BX 37                 // CTAs per batch (37*8 = 296 ~ one wave @ 2/SM)

#define AROW 520              // padded bf16 row stride (conflict-free ldmatrix)
#define ONE_BF16 0x3F80u

// Scratch (no allocations allowed)
__device__ float g_S[NB * NC * NC];   // S[b,i,k]
__device__ float g_cnt[NB * NC];      // cnt[b,k]
__device__ int   g_mode64;            // labels int64 in memory?

// ---------------------------------------------------------------------------
// Kernel 0: zero scratch + cheap label-dtype sniff (sampled).
// Odd 32-bit words of little-endian int64 labels (<19) are all zero; for
// genuine int32 labels they are uniform 0..18 -> OR over 8192 samples != 0.
// Sampled words < 16384 are in-bounds under either dtype.
// ---------------------------------------------------------------------------
__global__ void __launch_bounds__(256)
setup_kernel(const int* __restrict__ lab32) {
    int t = blockIdx.x * blockDim.x + threadIdx.x;
    if (t < NB * NC * NC) g_S[t] = 0.0f;
    if (t < NB * NC)      g_cnt[t] = 0.0f;
    if (t == 0)           g_mode64 = 1;

    int acc = 0;
    int nthreads = gridDim.x * blockDim.x;        // 3072
    for (int i = t; i < 8192; i += nthreads)
        acc |= lab32[2 * i + 1];
#pragma unroll
    for (int s = 16; s > 0; s >>= 1)
        acc |= __shfl_xor_sync(0xffffffffu, acc, s);
    if ((threadIdx.x & 31) == 0 && acc != 0)
        atomicExch(&g_mode64, 0);                 // int32 labels
}

// ---------------------------------------------------------------------------
// Kernel 1: per-batch GEMM  S[32p,24p] += Z_tile[32p,512] * Onehot[512,24p]
// via mma.m16n8k16 (bf16 -> f32). A row 19 is constant 1.0 -> row 19 of S
// is the class histogram (cnt). Onehot B-fragments built in registers.
// ---------------------------------------------------------------------------
__global__ void __launch_bounds__(256, 2)
gemm_scatter_kernel(const float* __restrict__ seg, const int* __restrict__ lab32) {
    __shared__ __align__(16) uint16_t Ash[32 * AROW];   // bf16 [32][520]
    __shared__ int   labels_sh[TPX];
    __shared__ float S_red[32][24];

    const int tid  = threadIdx.x;
    const int lane = tid & 31;
    const int wid  = tid >> 5;                    // 8 warps
    const int b    = blockIdx.y;
    const int mode64 = g_mode64;

    // One-time init: rows 19..31 (ones row + zero pad)
    for (int idx = tid; idx < 13 * AROW; idx += 256) {
        int r = 19 + idx / AROW, c = idx % AROW;
        Ash[r * AROW + c] = (r == 19) ? (uint16_t)ONE_BF16 : (uint16_t)0;
    }
    // zero the pad columns of rows 0..18 too (never read, but keep clean)
    for (int idx = tid; idx < 768; idx += 256)
        ((float*)S_red)[idx] = 0.0f;

    const float* zb = seg + (size_t)b * NC * HW;

    // fp32 accumulators: [mtile 2][ntile 3][frag 4]
    float acc[2][3][4];
#pragma unroll
    for (int m = 0; m < 2; m++)
#pragma unroll
        for (int n = 0; n < 3; n++)
#pragma unroll
            for (int f = 0; f < 4; f++) acc[m][n][f] = 0.0f;

    const uint32_t ash_base = (uint32_t)__cvta_generic_to_shared(Ash);

    for (int T = blockIdx.x; T < NTILES; T += BX) {
        const int tpx = T * TPX;

        __syncthreads();   // previous compute done before overwriting tiles

        // --- stage labels ---
        if (mode64) {
            const int4* lb = (const int4*)(lab32 + (size_t)b * HW * 2 + (size_t)tpx * 2);
            int4 w = lb[tid];                    // 256 threads x 2 labels
            labels_sh[2 * tid + 0] = w.x;
            labels_sh[2 * tid + 1] = w.z;
        } else if (tid < 128) {
            const int4* lb = (const int4*)(lab32 + (size_t)b * HW + tpx);
            int4 w = lb[tid];
            labels_sh[4 * tid + 0] = w.x;
            labels_sh[4 * tid + 1] = w.y;
            labels_sh[4 * tid + 2] = w.z;
            labels_sh[4 * tid + 3] = w.w;
        }

        // --- stage Z tile: 19 channels x 512 px, f32 -> bf16 ---
        // 19*128 float4 groups, 256 threads -> 9.5 iterations
        for (int idx = tid; idx < NC * 128; idx += 256) {
            int c = idx >> 7, j = idx & 127;     // channel, float4 index
            float4 v = ((const float4*)(zb + (size_t)c * HW + tpx))[j];
            uint32_t w0, w1;
            asm("cvt.rn.bf16x2.f32 %0, %1, %2;" : "=r"(w0) : "f"(v.y), "f"(v.x));
            asm("cvt.rn.bf16x2.f32 %0, %1, %2;" : "=r"(w1) : "f"(v.w), "f"(v.z));
            *(uint2*)((char*)Ash + c * (AROW * 2) + 8 * j) = make_uint2(w0, w1);
        }
        __syncthreads();

        // --- compute: each warp owns 64 pixels = 4 K-steps of 16 ---
        const int wbase = wid * 64;
#pragma unroll
        for (int ks = 0; ks < 4; ks++) {
            const int kb = wbase + ks * 16;

            // A fragments for both M-tiles via ldmatrix.x4
            uint32_t a[2][4];
            const uint32_t r = lane & 15, coff = (lane >> 4) << 3;
#pragma unroll
            for (int mt = 0; mt < 2; mt++) {
                uint32_t addr = ash_base + ((mt * 16 + r) * AROW + kb + coff) * 2;
                asm volatile("ldmatrix.sync.aligned.m8n8.x4.shared.b16 "
                             "{%0,%1,%2,%3}, [%4];"
                             : "=r"(a[mt][0]), "=r"(a[mt][1]),
                               "=r"(a[mt][2]), "=r"(a[mt][3])
                             : "r"(addr));
            }

            // labels for this lane's B rows
            const int kr = kb + ((lane & 3) << 1);
            const int l0 = labels_sh[kr + 0], l1 = labels_sh[kr + 1];
            const int l8 = labels_sh[kr + 8], l9 = labels_sh[kr + 9];
            const int ncol = lane >> 2;

#pragma unroll
            for (int nt = 0; nt < 3; nt++) {
                const int n = ncol + nt * 8;
                uint32_t b0 = (l0 == n ? ONE_BF16 : 0u) | (l1 == n ? (ONE_BF16 << 16) : 0u);
                uint32_t b1 = (l8 == n ? ONE_BF16 : 0u) | (l9 == n ? (ONE_BF16 << 16) : 0u);
#pragma unroll
                for (int mt = 0; mt < 2; mt++) {
                    asm volatile(
                        "mma.sync.aligned.m16n8k16.row.col.f32.bf16.bf16.f32 "
                        "{%0,%1,%2,%3}, {%4,%5,%6,%7}, {%8,%9}, {%0,%1,%2,%3};"
                        : "+f"(acc[mt][nt][0]), "+f"(acc[mt][nt][1]),
                          "+f"(acc[mt][nt][2]), "+f"(acc[mt][nt][3])
                        : "r"(a[mt][0]), "r"(a[mt][1]), "r"(a[mt][2]), "r"(a[mt][3]),
                          "r"(b0), "r"(b1));
                }
            }
        }
    }

    // --- CTA reduction: warps -> S_red (zeroed before the tile loop; no
    //     thread writes it during the loop) ---
    __syncthreads();
    {
        const int row0 = lane >> 2;
        const int col0 = (lane & 3) << 1;
#pragma unroll
        for (int mt = 0; mt < 2; mt++)
#pragma unroll
            for (int nt = 0; nt < 3; nt++) {
                int r0 = mt * 16 + row0, r1 = r0 + 8;
                int c0 = nt * 8 + col0,  c1 = c0 + 1;
                atomicAdd(&S_red[r0][c0], acc[mt][nt][0]);
                atomicAdd(&S_red[r0][c1], acc[mt][nt][1]);
                atomicAdd(&S_red[r1][c0], acc[mt][nt][2]);
                atomicAdd(&S_red[r1][c1], acc[mt][nt][3]);
            }
    }
    __syncthreads();

    // --- global flush: rows 0..18 -> g_S, row 19 -> g_cnt ---
    for (int idx = tid; idx < 20 * NC; idx += 256) {
        int r = idx / NC, c = idx % NC;
        float v = S_red[r][c];
        if (r < NC) atomicAdd(&g_S[(b * NC + r) * NC + c], v);
        else        atomicAdd(&g_cnt[b * NC + c], v);
    }
}

// ---------------------------------------------------------------------------
// Kernel 2: finalize — 2888 log terms in double, write the scalar loss
// ---------------------------------------------------------------------------
__global__ void __launch_bounds__(256)
finalize_kernel(float* __restrict__ out) {
    __shared__ double red[256];
    const int tid = threadIdx.x;
    const double eps = 2.220446049250313e-16;  // np.spacing(1)

    double acc = 0.0;
    for (int idx = tid; idx < NB * NC * NC; idx += 256) {
        int b = idx / (NC * NC);
        int rem = idx % (NC * NC);
        int i = rem / NC, k = rem % NC;
        float cnt_i = g_cnt[b * NC + i];
        float cnt_k = g_cnt[b * NC + k];
        double alpha = (cnt_i > 0.0f)
            ? (double)g_S[(b * NC + i) * NC + i] / (double)cnt_i : 0.0;
        double beta = (cnt_k > 0.0f)
            ? ((double)cnt_k - (double)g_S[(b * NC + i) * NC + k]) / (double)cnt_k
            : 0.0;
        acc += log(0.5 * (alpha + beta + eps));
    }
    red[tid] = acc;
    __syncthreads();
    for (int s = 128; s > 0; s >>= 1) {
        if (tid < s) red[tid] += red[tid + s];
        __syncthreads();
    }
    if (tid == 0) out[0] = (float)(-0.5 * red[0] / (double)NB);
}

// ---------------------------------------------------------------------------
extern "C" void kernel_launch(void* const* d_in, const int* in_sizes, int n_in,
                              void* d_out, int out_size) {
    const float* seg;
    const int*   lab32;
    if (in_sizes[0] > in_sizes[1]) {
        seg   = (const float*)d_in[0];
        lab32 = (const int*)d_in[1];
    } else {
        seg   = (const float*)d_in[1];
        lab32 = (const int*)d_in[0];
    }
    float* out = (float*)d_out;

    setup_kernel<<<12, 256>>>(lab32);

    dim3 grid(BX, NB);
    gemm_scatter_kernel<<<grid, 256>>>(seg, lab32);

    finalize_kernel<<<1, 256>>>(out);
}

// round 8
// speedup vs baseline: 2.3259x; 1.2112x over previous
#include <cuda_runtime.h>
#include <stdint.h>

#define NB 8
#define NC 19
#define HW (512 * 512)        // pixels per batch
#define TPX 512               // pixels per tile (K of the GEMM tile)
#define NTILES (HW / TPX)     // 512 tiles per batch
#define BX 37                 // CTAs per batch (37*8 = 296 = 2/SM wave)
#define ARF 516               // f32 row stride (516 % 32 == 4 -> conflict-free LDS)

#define SMEM_BYTES (2 * NC * ARF * 4 + 2 * 1024 * 4 + 20 * 24 * 4)  // 88544

// Scratch (no allocations allowed)
__device__ float g_S[NB * NC * NC];   // S[b,i,k] = sum_p z[b,i,p]*[label_p==k]
__device__ float g_cnt[NB * NC];      // cnt[b,k]
__device__ int   g_mode64;            // labels stored as int64?

// ---------------------------------------------------------------------------
// Kernel 0: zero scratch (grid-stride: correct for ANY grid) + dtype sniff.
// Odd 32-bit words of little-endian int64 labels (<19) are all zero; genuine
// int32 labels make the OR nonzero with overwhelming probability.
// ---------------------------------------------------------------------------
__global__ void __launch_bounds__(256)
setup_kernel(const int* __restrict__ lab32) {
    int t = blockIdx.x * blockDim.x + threadIdx.x;
    int nthreads = gridDim.x * blockDim.x;

    for (int i = t; i < NB * NC * NC; i += nthreads) g_S[i] = 0.0f;
    for (int i = t; i < NB * NC; i += nthreads)      g_cnt[i] = 0.0f;
    if (t == 0) g_mode64 = 1;

    int acc = 0;
    for (int i = t; i < 2048; i += nthreads)
        acc |= lab32[2 * i + 1];
#pragma unroll
    for (int s = 16; s > 0; s >>= 1)
        acc |= __shfl_xor_sync(0xffffffffu, acc, s);
    if ((threadIdx.x & 31) == 0 && acc != 0)
        atomicExch(&g_mode64, 0);
}

// ---------------------------------------------------------------------------
#define CVT_TF32(d, f) asm("cvt.rna.tf32.f32 %0, %1;" : "=r"(d) : "f"(f))

#define MMA_TF32(ac, A0, A1, A2, A3, B0, B1)                                  \
    asm volatile("mma.sync.aligned.m16n8k8.row.col.f32.tf32.tf32.f32 "        \
                 "{%0,%1,%2,%3}, {%4,%5,%6,%7}, {%8,%9}, {%0,%1,%2,%3};"      \
                 : "+f"((ac)[0]), "+f"((ac)[1]), "+f"((ac)[2]), "+f"((ac)[3]) \
                 : "r"(A0), "r"(A1), "r"(A2), "r"(A3), "r"(B0), "r"(B1))

__device__ __forceinline__ void cp16(void* sdst, const void* gsrc) {
    uint32_t s = (uint32_t)__cvta_generic_to_shared(sdst);
    asm volatile("cp.async.cg.shared.global [%0], [%1], 16;" :: "r"(s), "l"(gsrc));
}

// ---------------------------------------------------------------------------
// Kernel 1: per-batch GEMM  S[32,24] += Z_tile[32,512] * Onehot[512,24]
// tf32 mma, cp.async double-buffered pipeline, zero per-pixel atomics.
// A rows: 0..18 = channels, 19 = ones (-> cnt), 20..31 = 0 (implicit).
// ---------------------------------------------------------------------------
__global__ void __launch_bounds__(256, 2)
gemm_scatter_kernel(const float* __restrict__ seg, const int* __restrict__ lab32) {
    extern __shared__ __align__(16) char smem[];
    float* Abuf[2];
    Abuf[0] = (float*)smem;
    Abuf[1] = Abuf[0] + NC * ARF;
    int* Lbuf[2];
    Lbuf[0] = (int*)(Abuf[1] + NC * ARF);
    Lbuf[1] = Lbuf[0] + 1024;
    float* S_red = (float*)(Lbuf[1] + 1024);     // [20][24]

    const int tid  = threadIdx.x;
    const int lane = tid & 31;
    const int wid  = tid >> 5;
    const int b    = blockIdx.y;
    const int mode64 = g_mode64;                  // 0 or 1 (uniform)

    const float* zb  = seg + (size_t)b * NC * HW;
    const int*   lb  = lab32 + ((size_t)b * HW << mode64);

    for (int i = tid; i < 20 * 24; i += 256) S_red[i] = 0.0f;

    // accumulators: [ntile 3][frag 4] for each mtile
    float acc1[3][4], acc2[3][4];
#pragma unroll
    for (int n = 0; n < 3; n++)
#pragma unroll
        for (int f = 0; f < 4; f++) { acc1[n][f] = 0.0f; acc2[n][f] = 0.0f; }

    auto prefetch = [&](int T, int buf) {
        if (T >= NTILES) return;
        const int tpx = T * TPX;
        float* A = Abuf[buf];
        for (int idx = tid; idx < NC * 128; idx += 256) {
            int c = idx >> 7, j = idx & 127;
            cp16(A + c * ARF + 4 * j, zb + (size_t)c * HW + tpx + 4 * j);
        }
        if (mode64) {
            cp16(Lbuf[buf] + 4 * tid, lb + (size_t)tpx * 2 + 4 * tid);  // 4KB
        } else if (tid < 128) {
            cp16(Lbuf[buf] + 4 * tid, lb + tpx + 4 * tid);              // 2KB
        }
    };

    const int T0 = blockIdx.x;
    prefetch(T0, 0);
    asm volatile("cp.async.commit_group;");
    prefetch(T0 + BX, 1);
    asm volatile("cp.async.commit_group;");

    // per-thread fragment geometry
    const int g  = lane >> 2;          // group id (row within 8)
    const int c4 = lane & 3;           // col within 4 / k-row within 4
    const int wbase = wid * 64;        // this warp's 64-pixel k-slice
    const int r2 = 16 + g;             // mtile2 row (16..23)
    const int r2c = r2 < 19 ? r2 : 18; // clamped safe row
    const float sel1 = (r2 == 19) ? 1.0f : 0.0f;
    const float sel0 = (r2 < 19) ? 1.0f : 0.0f;

    int m = 0;
    for (int T = T0; T < NTILES; T += BX, m++) {
        const int buf = m & 1;
        asm volatile("cp.async.wait_group 1;");
        __syncthreads();

        const float* A = Abuf[buf];
        const int*   L = Lbuf[buf];
        const float* pA  = A + g * ARF + c4;
        const float* pA8 = A + (g + 8) * ARF + c4;
        const float* pA2 = A + r2c * ARF + c4;

#pragma unroll
        for (int ks = 0; ks < 8; ks++) {
            const int kb = wbase + ks * 8;

            float f0 = pA[kb], f1 = pA8[kb], f2 = pA[kb + 4], f3 = pA8[kb + 4];
            float h0 = pA2[kb] * sel0 + sel1;
            float h2 = pA2[kb + 4] * sel0 + sel1;

            uint32_t a0, a1, a2, a3, e0, e2;
            CVT_TF32(a0, f0); CVT_TF32(a1, f1);
            CVT_TF32(a2, f2); CVT_TF32(a3, f3);
            CVT_TF32(e0, h0); CVT_TF32(e2, h2);

            const int lA = L[(kb + c4) << mode64];
            const int lB = L[(kb + c4 + 4) << mode64];

#pragma unroll
            for (int nt = 0; nt < 3; nt++) {
                const int n = g + nt * 8;
                uint32_t b0 = (lA == n) ? 0x3F800000u : 0u;
                uint32_t b1 = (lB == n) ? 0x3F800000u : 0u;
                MMA_TF32(acc1[nt], a0, a1, a2, a3, b0, b1);
                MMA_TF32(acc2[nt], e0, 0u, e2, 0u, b0, b1);
            }
        }
        __syncthreads();

        prefetch(T + 2 * BX, buf);
        asm volatile("cp.async.commit_group;");
    }

    // ---- CTA reduction into S_red (rows 0..19 x cols 0..23) ----
    {
        const int cc = c4 * 2;
#pragma unroll
        for (int nt = 0; nt < 3; nt++) {
            const int nb8 = nt * 8 + cc;
            atomicAdd(&S_red[g * 24 + nb8],           acc1[nt][0]);
            atomicAdd(&S_red[g * 24 + nb8 + 1],       acc1[nt][1]);
            atomicAdd(&S_red[(g + 8) * 24 + nb8],     acc1[nt][2]);
            atomicAdd(&S_red[(g + 8) * 24 + nb8 + 1], acc1[nt][3]);
            if (r2 < 20) {  // rows 16..19 (rows 24..31 of mtile2 are zero)
                atomicAdd(&S_red[r2 * 24 + nb8],     acc2[nt][0]);
                atomicAdd(&S_red[r2 * 24 + nb8 + 1], acc2[nt][1]);
            }
        }
    }
    __syncthreads();

    // ---- global flush: rows 0..18 -> g_S, row 19 -> g_cnt ----
    for (int idx = tid; idx < 20 * NC; idx += 256) {
        int r = idx / NC, c = idx % NC;
        float v = S_red[r * 24 + c];
        if (r < NC) atomicAdd(&g_S[(b * NC + r) * NC + c], v);
        else        atomicAdd(&g_cnt[b * NC + c], v);
    }
}

// ---------------------------------------------------------------------------
// Kernel 2: finalize — 2888 log terms in double, write the scalar loss
// ---------------------------------------------------------------------------
__global__ void __launch_bounds__(256)
finalize_kernel(float* __restrict__ out) {
    __shared__ double red[256];
    const int tid = threadIdx.x;
    const double eps = 2.220446049250313e-16;  // np.spacing(1)

    double acc = 0.0;
    for (int idx = tid; idx < NB * NC * NC; idx += 256) {
        int b = idx / (NC * NC);
        int rem = idx % (NC * NC);
        int i = rem / NC, k = rem % NC;
        float cnt_i = g_cnt[b * NC + i];
        float cnt_k = g_cnt[b * NC + k];
        double alpha = (cnt_i > 0.0f)
            ? (double)g_S[(b * NC + i) * NC + i] / (double)cnt_i : 0.0;
        double beta = (cnt_k > 0.0f)
            ? ((double)cnt_k - (double)g_S[(b * NC + i) * NC + k]) / (double)cnt_k
            : 0.0;
        acc += log(0.5 * (alpha + beta + eps));
    }
    red[tid] = acc;
    __syncthreads();
    for (int s = 128; s > 0; s >>= 1) {
        if (tid < s) red[tid] += red[tid + s];
        __syncthreads();
    }
    if (tid == 0) out[0] = (float)(-0.5 * red[0] / (double)NB);
}

// ---------------------------------------------------------------------------
extern "C" void kernel_launch(void* const* d_in, const int* in_sizes, int n_in,
                              void* d_out, int out_size) {
    const float* seg;
    const int*   lab32;
    if (in_sizes[0] > in_sizes[1]) {
        seg   = (const float*)d_in[0];
        lab32 = (const int*)d_in[1];
    } else {
        seg   = (const float*)d_in[1];
        lab32 = (const int*)d_in[0];
    }
    float* out = (float*)d_out;

    cudaFuncSetAttribute(gemm_scatter_kernel,
                         cudaFuncAttributeMaxDynamicSharedMemorySize, SMEM_BYTES);

    setup_kernel<<<12, 256>>>(lab32);

    dim3 grid(BX, NB);
    gemm_scatter_kernel<<<grid, 256, SMEM_BYTES>>>(seg, lab32);

    finalize_kernel<<<1, 256>>>(out);
}